// round 1
// baseline (speedup 1.0000x reference)
#include <cuda_runtime.h>
#include <cuda_bf16.h>
#include <mma.h>
#include <math.h>
#include <stdint.h>

using namespace nvcuda;
typedef __nv_bfloat16 bf16;

#define TOK     16384      // B*N tokens
#define DMODEL  1024
#define HID     4096
#define NHEAD   8
#define DKH     128
#define NSEQ    256

// ---------------- scratch (static __device__, no allocations) ----------------
__device__ bf16  g_xn    [2L*TOK*DMODEL];    // LN outputs (reused for block-LN)
__device__ bf16  g_qkv   [6L*TOK*DMODEL];    // [stream][t][tok][d]
__device__ bf16  g_attn  [2L*TOK*DMODEL];    // merged attention out
__device__ float g_attres[2L*TOK*DMODEL];    // rgb_att / ir_att (fp32)
__device__ bf16  g_h1    [2L*TOK*HID];       // gelu(x W1 + b1)
__device__ bf16  g_wqkv  [6L*DMODEL*DMODEL];
__device__ bf16  g_wo    [2L*DMODEL*DMODEL];
__device__ bf16  g_w1    [2L*DMODEL*HID];
__device__ bf16  g_w2    [2L*HID*DMODEL];

// ---------------- helpers ----------------
__device__ __forceinline__ void cp_async16(void* d, const void* s) {
    unsigned ds = (unsigned)__cvta_generic_to_shared(d);
    asm volatile("cp.async.cg.shared.global [%0], [%1], 16;\n" :: "r"(ds), "l"(s));
}
__device__ __forceinline__ void cp_commit() { asm volatile("cp.async.commit_group;\n"); }

// ---------------- fp32 -> bf16 convert ----------------
__global__ void cvt_kernel(const float* __restrict__ src, bf16* __restrict__ dst) {
    long i = ((long)blockIdx.x * blockDim.x + threadIdx.x) * 4;
    float4 v = *reinterpret_cast<const float4*>(src + i);
    __nv_bfloat162 a = __floats2bfloat162_rn(v.x, v.y);
    __nv_bfloat162 b = __floats2bfloat162_rn(v.z, v.w);
    uint2 p;
    p.x = *reinterpret_cast<unsigned*>(&a);
    p.y = *reinterpret_cast<unsigned*>(&b);
    *reinterpret_cast<uint2*>(dst + i) = p;
}

// ---------------- LayerNorm (fp32 in -> bf16 out), one warp per row ----------------
__global__ void ln_kernel(const float* __restrict__ x, const float* __restrict__ gamma,
                          const float* __restrict__ beta, bf16* __restrict__ out) {
    int warp = threadIdx.x >> 5, lane = threadIdx.x & 31;
    long row = (long)blockIdx.x * 8 + warp;
    const float* xr = x + row * DMODEL;
    float4 v[8];
    float s = 0.f, s2 = 0.f;
#pragma unroll
    for (int i = 0; i < 8; i++) {
        v[i] = *reinterpret_cast<const float4*>(xr + i * 128 + lane * 4);
        s  += v[i].x + v[i].y + v[i].z + v[i].w;
        s2 += v[i].x*v[i].x + v[i].y*v[i].y + v[i].z*v[i].z + v[i].w*v[i].w;
    }
#pragma unroll
    for (int o = 16; o > 0; o >>= 1) {
        s  += __shfl_xor_sync(0xffffffffu, s,  o);
        s2 += __shfl_xor_sync(0xffffffffu, s2, o);
    }
    float m  = s * (1.f / 1024.f);
    float var = s2 * (1.f / 1024.f) - m * m;
    float rs = rsqrtf(var + 1e-5f);
    bf16* orow = out + row * DMODEL;
#pragma unroll
    for (int i = 0; i < 8; i++) {
        int c = i * 128 + lane * 4;
        float4 g4 = *reinterpret_cast<const float4*>(gamma + c);
        float4 b4 = *reinterpret_cast<const float4*>(beta + c);
        float o0 = (v[i].x - m) * rs * g4.x + b4.x;
        float o1 = (v[i].y - m) * rs * g4.y + b4.y;
        float o2 = (v[i].z - m) * rs * g4.z + b4.z;
        float o3 = (v[i].w - m) * rs * g4.w + b4.w;
        __nv_bfloat162 p0 = __floats2bfloat162_rn(o0, o1);
        __nv_bfloat162 p1 = __floats2bfloat162_rn(o2, o3);
        uint2 p;
        p.x = *reinterpret_cast<unsigned*>(&p0);
        p.y = *reinterpret_cast<unsigned*>(&p1);
        *reinterpret_cast<uint2*>(orow + c) = p;
    }
}

// ---------------- tiled wmma GEMM: C = A[M,K] @ B[K,N] + epilogue ----------------
// EPI 0: bf16 out = acc + bias
// EPI 1: bf16 out = gelu_exact(acc + bias)
// EPI 2: f32  out = coeffs[ci_res]*res + coeffs[ci_out]*(acc + bias)
#define BM 128
#define BN 128
#define BK 32

template <int EPI>
__global__ void __launch_bounds__(256, 2) gemm_kernel(
    const bf16* __restrict__ A, const bf16* __restrict__ B,
    const float* __restrict__ bias, const float* __restrict__ res,
    const float* __restrict__ coeffs, int ci_res, int ci_out,
    void* __restrict__ Cout, int M, int N, int K)
{
    __shared__ bf16 As[2][BM][BK + 8];
    __shared__ bf16 Bs[2][BK][BN + 8];
    __shared__ float epi_buf[8][256];

    int tid = threadIdx.x, wid = tid >> 5, lane = tid & 31;
    int warpM = wid & 1, warpN = wid >> 1;
    long bm = (long)blockIdx.y * BM;
    long bn = (long)blockIdx.x * BN;

    wmma::fragment<wmma::accumulator, 16, 16, 16, float> c[4][2];
#pragma unroll
    for (int i = 0; i < 4; i++)
#pragma unroll
        for (int j = 0; j < 2; j++) wmma::fill_fragment(c[i][j], 0.f);

    int KT = K / BK;
    // prefetch stage 0
    {
        long k0 = 0;
#pragma unroll
        for (int i = 0; i < 2; i++) {
            int v = tid + i * 256;
            int r = v >> 2, c8 = (v & 3) * 8;
            cp_async16(&As[0][r][c8], A + (bm + r) * K + k0 + c8);
        }
#pragma unroll
        for (int i = 0; i < 2; i++) {
            int v = tid + i * 256;
            int r = v >> 4, c8 = (v & 15) * 8;
            cp_async16(&Bs[0][r][c8], B + (k0 + r) * (long)N + bn + c8);
        }
        cp_commit();
    }

    for (int kt = 0; kt < KT; ++kt) {
        int st = kt & 1;
        if (kt + 1 < KT) {
            long k0 = (long)(kt + 1) * BK;
            int ns = st ^ 1;
#pragma unroll
            for (int i = 0; i < 2; i++) {
                int v = tid + i * 256;
                int r = v >> 2, c8 = (v & 3) * 8;
                cp_async16(&As[ns][r][c8], A + (bm + r) * K + k0 + c8);
            }
#pragma unroll
            for (int i = 0; i < 2; i++) {
                int v = tid + i * 256;
                int r = v >> 4, c8 = (v & 15) * 8;
                cp_async16(&Bs[ns][r][c8], B + (k0 + r) * (long)N + bn + c8);
            }
            cp_commit();
            asm volatile("cp.async.wait_group 1;\n");
        } else {
            asm volatile("cp.async.wait_group 0;\n");
        }
        __syncthreads();
#pragma unroll
        for (int ks = 0; ks < 2; ks++) {
            wmma::fragment<wmma::matrix_a, 16, 16, 16, bf16, wmma::row_major> a[4];
            wmma::fragment<wmma::matrix_b, 16, 16, 16, bf16, wmma::row_major> b[2];
#pragma unroll
            for (int i = 0; i < 4; i++)
                wmma::load_matrix_sync(a[i], &As[st][warpM * 64 + i * 16][ks * 16], BK + 8);
#pragma unroll
            for (int j = 0; j < 2; j++)
                wmma::load_matrix_sync(b[j], &Bs[st][ks * 16][warpN * 32 + j * 16], BN + 8);
#pragma unroll
            for (int i = 0; i < 4; i++)
#pragma unroll
                for (int j = 0; j < 2; j++)
                    wmma::mma_sync(c[i][j], a[i], b[j], c[i][j]);
        }
        __syncthreads();
    }

    // epilogue
#pragma unroll
    for (int i = 0; i < 4; i++) {
#pragma unroll
        for (int j = 0; j < 2; j++) {
            wmma::store_matrix_sync(epi_buf[wid], c[i][j], 16, wmma::mem_row_major);
            __syncwarp();
            long r0 = bm + warpM * 64 + i * 16;
            long c0 = bn + warpN * 32 + j * 16;
#pragma unroll
            for (int e = 0; e < 8; e++) {
                int idx = lane + e * 32;
                int rr = idx >> 4, cc = idx & 15;
                long gr = r0 + rr, gc = c0 + cc;
                float val = epi_buf[wid][idx] + bias[gc];
                if (EPI == 0) {
                    ((bf16*)Cout)[gr * N + gc] = __float2bfloat16(val);
                } else if (EPI == 1) {
                    float gel = 0.5f * val * (1.f + erff(val * 0.70710678118654752f));
                    ((bf16*)Cout)[gr * N + gc] = __float2bfloat16(gel);
                } else {
                    float o = coeffs[ci_res] * res[gr * N + gc] + coeffs[ci_out] * val;
                    ((float*)Cout)[gr * N + gc] = o;
                }
            }
            __syncwarp();
        }
    }
}

// ---------------- fused cross-attention, one CTA per (stream, b, h) ----------------
// smem: K[256x136] bf16, V[256x136] bf16, Q[32x136] bf16, S[32x256] f32 (reused as O f32), P[32x264] bf16
#define SMEM_ATT 197632

__global__ void __launch_bounds__(256) attn_kernel() {
    extern __shared__ char smraw[];
    bf16*  Ks = (bf16*)smraw;
    bf16*  Vs = Ks + 256 * 136;
    bf16*  Qs = Vs + 256 * 136;
    float* Ss = (float*)(Qs + 32 * 136);
    bf16*  Ps = (bf16*)(Ss + 32 * 256);
    float* Os = Ss;

    int tid = threadIdx.x, wid = tid >> 5, lane = tid & 31;
    int bx = blockIdx.x;
    int s  = bx >> 9;        // output stream
    int bh = bx & 511;
    int b = bh >> 3, h = bh & 7;

    const bf16* Qg = g_qkv + ((long)((1 - s) * 3 + 0)) * TOK * DMODEL + ((long)b * NSEQ) * DMODEL + h * DKH;
    const bf16* Kg = g_qkv + ((long)(s * 3 + 1)) * TOK * DMODEL + ((long)b * NSEQ) * DMODEL + h * DKH;
    const bf16* Vg = g_qkv + ((long)(s * 3 + 2)) * TOK * DMODEL + ((long)b * NSEQ) * DMODEL + h * DKH;
    bf16*       Og = g_attn + ((long)s) * TOK * DMODEL + ((long)b * NSEQ) * DMODEL + h * DKH;

#pragma unroll
    for (int i = 0; i < 16; i++) {
        int v = tid + i * 256;
        int r = v >> 4, c8 = (v & 15) * 8;
        *(uint4*)&Ks[r * 136 + c8] = *(const uint4*)&Kg[(long)r * DMODEL + c8];
        *(uint4*)&Vs[r * 136 + c8] = *(const uint4*)&Vg[(long)r * DMODEL + c8];
    }
    __syncthreads();

    const float scale = 0.08838834764831845f;  // 1/sqrt(128)

    for (int qc = 0; qc < 8; qc++) {
        // load 32 query rows
#pragma unroll
        for (int i = 0; i < 2; i++) {
            int v = tid + i * 256;
            int r = v >> 4, c8 = (v & 15) * 8;
            *(uint4*)&Qs[r * 136 + c8] = *(const uint4*)&Qg[(long)(qc * 32 + r) * DMODEL + c8];
        }
        __syncthreads();

        // S = Q K^T * scale : warp w does cols [w*32, w*32+32)
        {
            wmma::fragment<wmma::accumulator, 16, 16, 16, float> c[2][2];
#pragma unroll
            for (int i = 0; i < 2; i++)
#pragma unroll
                for (int j = 0; j < 2; j++) wmma::fill_fragment(c[i][j], 0.f);
#pragma unroll
            for (int kt = 0; kt < 8; kt++) {
                wmma::fragment<wmma::matrix_a, 16, 16, 16, bf16, wmma::row_major> a[2];
                wmma::fragment<wmma::matrix_b, 16, 16, 16, bf16, wmma::col_major> bb[2];
#pragma unroll
                for (int i = 0; i < 2; i++)
                    wmma::load_matrix_sync(a[i], &Qs[(i * 16) * 136 + kt * 16], 136);
#pragma unroll
                for (int j = 0; j < 2; j++)
                    wmma::load_matrix_sync(bb[j], &Ks[(wid * 32 + j * 16) * 136 + kt * 16], 136);
#pragma unroll
                for (int i = 0; i < 2; i++)
#pragma unroll
                    for (int j = 0; j < 2; j++)
                        wmma::mma_sync(c[i][j], a[i], bb[j], c[i][j]);
            }
#pragma unroll
            for (int i = 0; i < 2; i++)
#pragma unroll
                for (int j = 0; j < 2; j++) {
#pragma unroll
                    for (int t = 0; t < c[i][j].num_elements; t++) c[i][j].x[t] *= scale;
                    wmma::store_matrix_sync(&Ss[(i * 16) * 256 + wid * 32 + j * 16],
                                            c[i][j], 256, wmma::mem_row_major);
                }
        }
        __syncthreads();

        // softmax: warp w handles rows 4w..4w+3
        {
#pragma unroll
            for (int rq = 0; rq < 4; rq++) {
                int row = wid * 4 + rq;
                float* srow = Ss + row * 256;
                float vals[8];
                float mx = -1e30f;
#pragma unroll
                for (int i = 0; i < 8; i++) { vals[i] = srow[lane + i * 32]; mx = fmaxf(mx, vals[i]); }
#pragma unroll
                for (int o = 16; o > 0; o >>= 1) mx = fmaxf(mx, __shfl_xor_sync(0xffffffffu, mx, o));
                float sum = 0.f;
#pragma unroll
                for (int i = 0; i < 8; i++) { vals[i] = __expf(vals[i] - mx); sum += vals[i]; }
#pragma unroll
                for (int o = 16; o > 0; o >>= 1) sum += __shfl_xor_sync(0xffffffffu, sum, o);
                float inv = 1.f / sum;
#pragma unroll
                for (int i = 0; i < 8; i++)
                    Ps[row * 264 + lane + i * 32] = __float2bfloat16(vals[i] * inv);
            }
        }
        __syncthreads();

        // O = P @ V : warp w does dim cols [w*16, w*16+16)
        {
            wmma::fragment<wmma::accumulator, 16, 16, 16, float> c2[2];
#pragma unroll
            for (int i = 0; i < 2; i++) wmma::fill_fragment(c2[i], 0.f);
#pragma unroll
            for (int kt = 0; kt < 16; kt++) {
                wmma::fragment<wmma::matrix_a, 16, 16, 16, bf16, wmma::row_major> a[2];
                wmma::fragment<wmma::matrix_b, 16, 16, 16, bf16, wmma::row_major> bb;
#pragma unroll
                for (int i = 0; i < 2; i++)
                    wmma::load_matrix_sync(a[i], &Ps[(i * 16) * 264 + kt * 16], 264);
                wmma::load_matrix_sync(bb, &Vs[(kt * 16) * 136 + wid * 16], 136);
#pragma unroll
                for (int i = 0; i < 2; i++) wmma::mma_sync(c2[i], a[i], bb, c2[i]);
            }
#pragma unroll
            for (int i = 0; i < 2; i++)
                wmma::store_matrix_sync(&Os[(i * 16) * 128 + wid * 16], c2[i], 128, wmma::mem_row_major);
        }
        __syncthreads();

        // write out (bf16)
#pragma unroll
        for (int i = 0; i < 16; i++) {
            int e = tid + i * 256;
            int r = e >> 7, cc = e & 127;
            Og[(long)(qc * 32 + r) * DMODEL + cc] = __float2bfloat16(Os[r * 128 + cc]);
        }
        __syncthreads();
    }
}

// ---------------- host ----------------
extern "C" void kernel_launch(void* const* d_in, const int* in_sizes, int n_in,
                              void* d_out, int out_size) {
    const float* rgb   = (const float*)d_in[0];
    const float* ir    = (const float*)d_in[1];
    const float* ln1g  = (const float*)d_in[2];
    const float* ln1b  = (const float*)d_in[3];
    const float* ln2g  = (const float*)d_in[4];
    const float* ln2b  = (const float*)d_in[5];
    const float* Wqv   = (const float*)d_in[6];
    const float* bqv   = (const float*)d_in[7];
    const float* Wqi   = (const float*)d_in[8];
    const float* bqi   = (const float*)d_in[9];
    const float* Wov   = (const float*)d_in[10];
    const float* bov   = (const float*)d_in[11];
    const float* Woi   = (const float*)d_in[12];
    const float* boi   = (const float*)d_in[13];
    const float* blkg  = (const float*)d_in[14];
    const float* blkb  = (const float*)d_in[15];
    const float* W1v   = (const float*)d_in[16];
    const float* b1v   = (const float*)d_in[17];
    const float* W2v   = (const float*)d_in[18];
    const float* b2v   = (const float*)d_in[19];
    const float* W1i   = (const float*)d_in[20];
    const float* b1i   = (const float*)d_in[21];
    const float* W2i   = (const float*)d_in[22];
    const float* b2i   = (const float*)d_in[23];
    const float* coeffs = (const float*)d_in[24];

    bf16 *xn, *qkv, *attn, *h1, *wqkv, *wo, *w1, *w2;
    float* attres;
    cudaGetSymbolAddress((void**)&xn, g_xn);
    cudaGetSymbolAddress((void**)&qkv, g_qkv);
    cudaGetSymbolAddress((void**)&attn, g_attn);
    cudaGetSymbolAddress((void**)&attres, g_attres);
    cudaGetSymbolAddress((void**)&h1, g_h1);
    cudaGetSymbolAddress((void**)&wqkv, g_wqkv);
    cudaGetSymbolAddress((void**)&wo, g_wo);
    cudaGetSymbolAddress((void**)&w1, g_w1);
    cudaGetSymbolAddress((void**)&w2, g_w2);

    // weight converts (fp32 -> bf16)
    const long DD = (long)DMODEL * DMODEL;
    cvt_kernel<<<(3 * DD) / 1024, 256>>>(Wqv, wqkv);
    cvt_kernel<<<(3 * DD) / 1024, 256>>>(Wqi, wqkv + 3 * DD);
    cvt_kernel<<<DD / 1024, 256>>>(Wov, wo);
    cvt_kernel<<<DD / 1024, 256>>>(Woi, wo + DD);
    cvt_kernel<<<((long)DMODEL * HID) / 1024, 256>>>(W1v, w1);
    cvt_kernel<<<((long)DMODEL * HID) / 1024, 256>>>(W1i, w1 + (long)DMODEL * HID);
    cvt_kernel<<<((long)HID * DMODEL) / 1024, 256>>>(W2v, w2);
    cvt_kernel<<<((long)HID * DMODEL) / 1024, 256>>>(W2i, w2 + (long)HID * DMODEL);

    // LN1/LN2 per stream
    ln_kernel<<<TOK / 8, 256>>>(rgb, ln1g, ln1b, xn);
    ln_kernel<<<TOK / 8, 256>>>(ir, ln2g, ln2b, xn + (long)TOK * DMODEL);

    // QKV projections
    const long TD = (long)TOK * DMODEL;
    for (int s = 0; s < 2; s++) {
        const float* bq = s ? bqi : bqv;
        for (int t = 0; t < 3; t++) {
            gemm_kernel<0><<<dim3(DMODEL / BN, TOK / BM), 256>>>(
                xn + s * TD, wqkv + ((long)(s * 3 + t)) * DD, bq + t * DMODEL,
                nullptr, nullptr, 0, 0,
                qkv + ((long)(s * 3 + t)) * TD, TOK, DMODEL, DMODEL);
        }
    }

    // fused cross attention
    cudaFuncSetAttribute(attn_kernel, cudaFuncAttributeMaxDynamicSharedMemorySize, SMEM_ATT);
    attn_kernel<<<1024, 256, SMEM_ATT>>>();

    // output projection + coeff residual -> fp32 attres
    for (int s = 0; s < 2; s++) {
        gemm_kernel<2><<<dim3(DMODEL / BN, TOK / BM), 256>>>(
            attn + s * TD, wo + s * DD, s ? boi : bov,
            s ? ir : rgb, coeffs, 2 * s, 2 * s + 1,
            attres + s * TD, TOK, DMODEL, DMODEL);
    }

    // block LN (shared params)
    ln_kernel<<<TOK / 8, 256>>>(attres, blkg, blkb, xn);
    ln_kernel<<<TOK / 8, 256>>>(attres + TD, blkg, blkb, xn + TD);

    // MLP1 (gelu)
    for (int s = 0; s < 2; s++) {
        gemm_kernel<1><<<dim3(HID / BN, TOK / BM), 256>>>(
            xn + s * TD, w1 + (long)s * DMODEL * HID, s ? b1i : b1v,
            nullptr, nullptr, 0, 0,
            h1 + (long)s * TOK * HID, TOK, HID, DMODEL);
    }

    // MLP2 + coeff residual -> d_out (fp32)
    for (int s = 0; s < 2; s++) {
        gemm_kernel<2><<<dim3(DMODEL / BN, TOK / BM), 256>>>(
            h1 + (long)s * TOK * HID, w2 + (long)s * HID * DMODEL, s ? b2i : b2v,
            attres + s * TD, coeffs, 4 + 2 * s, 5 + 2 * s,
            (float*)d_out + s * TD, TOK, DMODEL, HID);
    }
}